// round 14
// baseline (speedup 1.0000x reference)
#include <cuda_runtime.h>
#include <cuda_fp16.h>
#include <math.h>

#define N_NODES 2560
#define N_EDGES 163840
#define HEADS   4
#define IN_C    32
#define C_HID   128
#define F_HID   512
#define OUT_E   40
#define EPS_BN  1e-5f
#define CAP     192

// ---------------- scratch (device globals) ----------------------------------
__device__ __half d_h[N_NODES * F_HID];
__device__ __half d_W2h[F_HID * F_HID];
__device__ float d_agg[N_NODES * F_HID];
__device__ __align__(16) float d_as[N_NODES * HEADS];
__device__ __align__(16) float d_ad[N_NODES * HEADS];
__device__ int   d_cursor[N_NODES * 32];
__device__ int   d_csr_src[N_NODES * CAP];
__device__ float d_csr_ew[N_NODES * CAP];
__device__ float d_coef[2 * HEADS];
__device__ float d_bnsum[F_HID];
__device__ float d_bnsq[F_HID];
__device__ int   d_ticket;
__device__ int   d_flag1;
__device__ int   d_flag2;
__device__ __align__(16) float d_scale[F_HID];
__device__ __align__(16) float d_shift[F_HID];

__device__ __forceinline__ unsigned smem_u32(const void* p) {
    return (unsigned)__cvta_generic_to_shared(p);
}

// ---------------- prep: convW + out-init + coef + zeroing (128 blocks) ------
__global__ void __launch_bounds__(256) k_prep(const float* __restrict__ W2,
                                              const float* __restrict__ adj,
                                              const float* __restrict__ bfc,
                                              const int* __restrict__ mask,
                                              float* __restrict__ out,
                                              const float* __restrict__ We1,
                                              const float* __restrict__ ae1,
                                              const float* __restrict__ We2,
                                              const float* __restrict__ ae2) {
    int gt = blockIdx.x * blockDim.x + threadIdx.x;   // 0..32767
    {
        int i = gt * 8;
        float4 f0 = *(const float4*)(W2 + i);
        float4 f1 = *(const float4*)(W2 + i + 4);
        __half2 h0 = __floats2half2_rn(f0.x, f0.y);
        __half2 h1 = __floats2half2_rn(f0.z, f0.w);
        __half2 h2 = __floats2half2_rn(f1.x, f1.y);
        __half2 h3 = __floats2half2_rn(f1.z, f1.w);
        uint4 pk;
        pk.x = *(unsigned*)&h0; pk.y = *(unsigned*)&h1;
        pk.z = *(unsigned*)&h2; pk.w = *(unsigned*)&h3;
        *(uint4*)(d_W2h + i) = pk;
    }
    for (int i = gt; i < N_NODES * OUT_E; i += 32768) {
        int n = i / OUT_E;
        int j = i - n * OUT_E;
        out[i] = adj[i] + bfc[j] * (float)mask[n];
    }
    if (gt < N_NODES) d_cursor[gt << 5] = 0;
    if (gt < N_NODES * HEADS) { d_as[gt] = 0.0f; d_ad[gt] = 0.0f; }
    if (gt < F_HID) { d_bnsum[gt] = 0.0f; d_bnsq[gt] = 0.0f; }
    if (gt == 0) { d_ticket = 0; d_flag1 = 0; d_flag2 = 0; }
    if (blockIdx.x == 0) {
        int w = threadIdx.x >> 5;
        int lane = threadIdx.x & 31;
        const float* We = (w < 4) ? We1 : We2;
        const float* ae = (w < 4) ? ae1 : ae2;
        int h = w & 3;
        float s = 0.0f;
        for (int i = lane; i < C_HID; i += 32) s += We[h * C_HID + i] * ae[h * C_HID + i];
#pragma unroll
        for (int o = 16; o; o >>= 1) s += __shfl_down_sync(0xffffffffu, s, o);
        if (lane == 0) d_coef[w] = s;
    }
}

// ---------------- fused: fill buckets (blocks 0..639) + GEMM1 (640..959) ----
__global__ void __launch_bounds__(256) k_fill_gemm1(const int* __restrict__ ei,
                                                    const float* __restrict__ pos,
                                                    const float* __restrict__ A,
                                                    const float* __restrict__ B,
                                                    const float* __restrict__ att_s,
                                                    const float* __restrict__ att_d) {
    if (blockIdx.x < 640) {
        int e = blockIdx.x * 256 + threadIdx.x;
        if (e >= N_EDGES) return;
        int s = ei[e], d = ei[N_EDGES + e];
        float dx = pos[2 * s] - pos[2 * d];
        float dy = pos[2 * s + 1] - pos[2 * d + 1];
        float ew = 1.0f / (sqrtf(dx * dx + dy * dy) + 1e-6f);
        int p = atomicAdd(&d_cursor[d << 5], 1);
        if (p < CAP) {
            d_csr_src[d * CAP + p] = s;
            d_csr_ew[d * CAP + p] = ew;
        }
        return;
    }
    // ---- GEMM1: 64x64 tile, K=32, attdot epilogue ----
    const int Nc = F_HID, K = IN_C;
    __shared__ float As[16][64];
    __shared__ float Bs[16][64];
    int blk = blockIdx.x - 640;          // 0..319
    int bm = (blk >> 3) * 64, bn = (blk & 7) * 64;
    int tid = threadIdx.x;
    int tx = tid & 15, ty = tid >> 4;
    int ar = tid >> 2, ac = (tid & 3) << 2;
    int br = tid >> 4, bc = (tid & 15) << 2;
    float acc[4][4] = {};

    for (int k0 = 0; k0 < K; k0 += 16) {
        float4 av = *(const float4*)(A + (size_t)(bm + ar) * K + k0 + ac);
        As[ac + 0][ar] = av.x; As[ac + 1][ar] = av.y;
        As[ac + 2][ar] = av.z; As[ac + 3][ar] = av.w;
        *(float4*)&Bs[br][bc] = *(const float4*)(B + (size_t)(k0 + br) * Nc + bn + bc);
        __syncthreads();
#pragma unroll
        for (int k = 0; k < 16; k++) {
            float a[4], b[4];
#pragma unroll
            for (int i = 0; i < 4; i++) a[i] = As[k][(ty << 2) + i];
#pragma unroll
            for (int j = 0; j < 4; j++) b[j] = Bs[k][(tx << 2) + j];
#pragma unroll
            for (int i = 0; i < 4; i++)
#pragma unroll
                for (int j = 0; j < 4; j++) acc[i][j] += a[i] * b[j];
        }
        __syncthreads();
    }

    int h = bn >> 7;
    int colbase = (bn & 127) + (tx << 2);
    float4 asv = *(const float4*)(att_s + h * C_HID + colbase);
    float4 adv = *(const float4*)(att_d + h * C_HID + colbase);
#pragma unroll
    for (int i = 0; i < 4; i++) {
        int row = bm + (ty << 2) + i;
        __half2 p0 = __floats2half2_rn(acc[i][0], acc[i][1]);
        __half2 p1 = __floats2half2_rn(acc[i][2], acc[i][3]);
        uint2 pk;
        pk.x = *(unsigned*)&p0;
        pk.y = *(unsigned*)&p1;
        *(uint2*)(d_h + (size_t)row * F_HID + bn + (tx << 2)) = pk;
        float ps = acc[i][0] * asv.x + acc[i][1] * asv.y + acc[i][2] * asv.z + acc[i][3] * asv.w;
        float pd = acc[i][0] * adv.x + acc[i][1] * adv.y + acc[i][2] * adv.z + acc[i][3] * adv.w;
#pragma unroll
        for (int o = 8; o; o >>= 1) {
            ps += __shfl_xor_sync(0xffffffffu, ps, o);
            pd += __shfl_xor_sync(0xffffffffu, pd, o);
        }
        if (tx == 0) {
            atomicAdd(&d_as[row * 4 + h], ps);
            atomicAdd(&d_ad[row * 4 + h], pd);
        }
    }
}

// ---------------- GEMM2: BN1 stats + barrier + 64x32 ping-pong HMMA ---------
// grid (16, 40) = 640 blocks; each block 64 M-rows x 32 N-cols.
#define APAD_A 72
#define APAD_B 40
__global__ void __launch_bounds__(256) k_gemm2_mma(const float* __restrict__ A,
                                                   const float* __restrict__ att_s,
                                                   const float* __restrict__ att_d,
                                                   const float* __restrict__ g,
                                                   const float* __restrict__ b) {
    __shared__ __half As[2][64 * APAD_A];
    __shared__ __half Bs[2][64 * APAD_B];
    __shared__ float s_sc[F_HID];
    __shared__ float s_sh[F_HID];
    __shared__ int s_last;
    int tid = threadIdx.x;
    int lane = tid & 31, wid = tid >> 5;
    int warp_m = wid >> 1, warp_n = wid & 1;    // 4x2 warps, 16x16 per warp
    int bm = blockIdx.y * 64, bn = blockIdx.x * 32;
    int nblocks = gridDim.x * gridDim.y;                 // 640
    int lb = blockIdx.y * gridDim.x + blockIdx.x;        // 0..639

    int arow = tid >> 2, aseg = (tid & 3) * 16;  // A: 64 rows x 64 k
    int brow = tid >> 2, bseg = (tid & 3) * 8;   // B: 64 k-rows x 32 n

    // prefetch tile 0 (independent of BN) — overlaps the barrier below
    float4 aReg[4];
    uint4  bReg;
    {
        const float* Ap = A + (size_t)(bm + arow) * F_HID + aseg;
#pragma unroll
        for (int j = 0; j < 4; j++) aReg[j] = *(const float4*)(Ap + j * 4);
        bReg = *(const uint4*)(d_W2h + (size_t)brow * F_HID + bn + bseg);
    }

    // ---- BN1 partial stats: rows lb*4..+3, channels tid, tid+256 ----
    {
        int r0 = lb * 4;
        float s0 = 0.0f, q0 = 0.0f, s1 = 0.0f, q1 = 0.0f;
#pragma unroll
        for (int r = 0; r < 4; r++) {
            float v0 = d_agg[(size_t)(r0 + r) * F_HID + tid];
            float v1 = d_agg[(size_t)(r0 + r) * F_HID + tid + 256];
            s0 += v0; q0 += v0 * v0;
            s1 += v1; q1 += v1 * v1;
        }
        atomicAdd(&d_bnsum[tid], s0);
        atomicAdd(&d_bnsq[tid], q0);
        atomicAdd(&d_bnsum[tid + 256], s1);
        atomicAdd(&d_bnsq[tid + 256], q1);
    }
    __threadfence();
    __syncthreads();
    if (tid == 0) s_last = (atomicAdd(&d_ticket, 1) == nblocks - 1);
    __syncthreads();
    if (s_last) {
        for (int c = tid; c < F_HID; c += 256) {
            float mean = d_bnsum[c] * (1.0f / N_NODES);
            float var  = d_bnsq[c] * (1.0f / N_NODES) - mean * mean;
            float sc = rsqrtf(var + EPS_BN) * g[c];
            d_scale[c] = sc;
            d_shift[c] = b[c] - mean * sc;
            d_bnsum[c] = 0.0f;
            d_bnsq[c] = 0.0f;
        }
        for (int i = tid; i < N_NODES * HEADS; i += 256) {
            d_as[i] = 0.0f;
            d_ad[i] = 0.0f;
        }
        __threadfence();
        __syncthreads();
        if (tid == 0) { d_ticket = 0; atomicExch(&d_flag1, 1); }
    }
    if (tid == 0) {
        while (atomicAdd(&d_flag1, 0) == 0) __nanosleep(64);
    }
    __syncthreads();
    __threadfence();

    for (int i = tid; i < F_HID; i += 256) {
        s_sc[i] = d_scale[i];
        s_sh[i] = d_shift[i];
    }
    __syncthreads();

    float acc[2][4] = {};
    // store tile 0 (BN + cvt)
    {
        int cb = aseg;
#pragma unroll
        for (int j = 0; j < 4; j++) {
            float4 f = aReg[j];
            float4 sc = *(const float4*)(s_sc + cb + j * 4);
            float4 sh = *(const float4*)(s_sh + cb + j * 4);
            f.x = fmaxf(f.x * sc.x + sh.x, 0.0f);
            f.y = fmaxf(f.y * sc.y + sh.y, 0.0f);
            f.z = fmaxf(f.z * sc.z + sh.z, 0.0f);
            f.w = fmaxf(f.w * sc.w + sh.w, 0.0f);
            __half2 h0 = __floats2half2_rn(f.x, f.y);
            __half2 h1 = __floats2half2_rn(f.z, f.w);
            uint2 pk; pk.x = *(unsigned*)&h0; pk.y = *(unsigned*)&h1;
            *(uint2*)(As[0] + arow * APAD_A + aseg + j * 4) = pk;
        }
        *(uint4*)(Bs[0] + brow * APAD_B + bseg) = bReg;
    }
    __syncthreads();

    for (int kt = 0; kt < 8; kt++) {
        int cur = kt & 1, nxt = cur ^ 1;
        if (kt < 7) {
            int k0n = (kt + 1) * 64;
            const float* Ap = A + (size_t)(bm + arow) * F_HID + k0n + aseg;
#pragma unroll
            for (int j = 0; j < 4; j++) aReg[j] = *(const float4*)(Ap + j * 4);
            bReg = *(const uint4*)(d_W2h + (size_t)(k0n + brow) * F_HID + bn + bseg);
        }

#pragma unroll
        for (int kk = 0; kk < 64; kk += 16) {
            unsigned aF[4], bF[4];
            {
                unsigned addr = smem_u32(As[cur] + (warp_m * 16 + (lane & 15)) * APAD_A
                                            + kk + ((lane >> 4) << 3));
                asm volatile("ldmatrix.sync.aligned.m8n8.x4.shared.b16 {%0,%1,%2,%3}, [%4];"
                             : "=r"(aF[0]), "=r"(aF[1]), "=r"(aF[2]), "=r"(aF[3])
                             : "r"(addr));
            }
            {
                unsigned addr = smem_u32(Bs[cur] + (kk + (lane & 15)) * APAD_B
                                            + warp_n * 16 + ((lane >> 4) << 3));
                asm volatile("ldmatrix.sync.aligned.m8n8.x4.trans.shared.b16 {%0,%1,%2,%3}, [%4];"
                             : "=r"(bF[0]), "=r"(bF[1]), "=r"(bF[2]), "=r"(bF[3])
                             : "r"(addr));
            }
#pragma unroll
            for (int ni = 0; ni < 2; ni++) {
                asm volatile(
                    "mma.sync.aligned.m16n8k16.row.col.f32.f16.f16.f32 "
                    "{%0,%1,%2,%3}, {%4,%5,%6,%7}, {%8,%9}, {%0,%1,%2,%3};"
                    : "+f"(acc[ni][0]), "+f"(acc[ni][1]),
                      "+f"(acc[ni][2]), "+f"(acc[ni][3])
                    : "r"(aF[0]), "r"(aF[1]), "r"(aF[2]), "r"(aF[3]),
                      "r"(bF[ni * 2]), "r"(bF[ni * 2 + 1]));
            }
        }

        if (kt < 7) {
            int cb = (kt + 1) * 64 + aseg;
#pragma unroll
            for (int j = 0; j < 4; j++) {
                float4 f = aReg[j];
                float4 sc = *(const float4*)(s_sc + cb + j * 4);
                float4 sh = *(const float4*)(s_sh + cb + j * 4);
                f.x = fmaxf(f.x * sc.x + sh.x, 0.0f);
                f.y = fmaxf(f.y * sc.y + sh.y, 0.0f);
                f.z = fmaxf(f.z * sc.z + sh.z, 0.0f);
                f.w = fmaxf(f.w * sc.w + sh.w, 0.0f);
                __half2 h0 = __floats2half2_rn(f.x, f.y);
                __half2 h1 = __floats2half2_rn(f.z, f.w);
                uint2 pk; pk.x = *(unsigned*)&h0; pk.y = *(unsigned*)&h1;
                *(uint2*)(As[nxt] + arow * APAD_A + aseg + j * 4) = pk;
            }
            *(uint4*)(Bs[nxt] + brow * APAD_B + bseg) = bReg;
            __syncthreads();
        }
    }

    // epilogue: fp16 store + attention dot partials
    int h = bn >> 7;
    int colh = (bn & 127) + warp_n * 16;
    float asv[2][2], adv[2][2];
#pragma unroll
    for (int ni = 0; ni < 2; ni++) {
        int c0 = colh + ni * 8 + (lane & 3) * 2;
        asv[ni][0] = att_s[h * C_HID + c0];
        asv[ni][1] = att_s[h * C_HID + c0 + 1];
        adv[ni][0] = att_d[h * C_HID + c0];
        adv[ni][1] = att_d[h * C_HID + c0 + 1];
    }
    {
        int row0 = bm + warp_m * 16 + (lane >> 2);
        int row1 = row0 + 8;
        float ps0 = 0.0f, pd0 = 0.0f, ps1 = 0.0f, pd1 = 0.0f;
#pragma unroll
        for (int ni = 0; ni < 2; ni++) {
            int col = bn + warp_n * 16 + ni * 8 + (lane & 3) * 2;
            __half2 h0 = __floats2half2_rn(acc[ni][0], acc[ni][1]);
            __half2 h1 = __floats2half2_rn(acc[ni][2], acc[ni][3]);
            *(__half2*)(d_h + (size_t)row0 * F_HID + col) = h0;
            *(__half2*)(d_h + (size_t)row1 * F_HID + col) = h1;
            ps0 += acc[ni][0] * asv[ni][0] + acc[ni][1] * asv[ni][1];
            ps1 += acc[ni][2] * asv[ni][0] + acc[ni][3] * asv[ni][1];
            pd0 += acc[ni][0] * adv[ni][0] + acc[ni][1] * adv[ni][1];
            pd1 += acc[ni][2] * adv[ni][0] + acc[ni][3] * adv[ni][1];
        }
#pragma unroll
        for (int o = 1; o < 4; o <<= 1) {
            ps0 += __shfl_xor_sync(0xffffffffu, ps0, o);
            ps1 += __shfl_xor_sync(0xffffffffu, ps1, o);
            pd0 += __shfl_xor_sync(0xffffffffu, pd0, o);
            pd1 += __shfl_xor_sync(0xffffffffu, pd1, o);
        }
        if ((lane & 3) == 0) {
            atomicAdd(&d_as[row0 * 4 + h], ps0);
            atomicAdd(&d_ad[row0 * 4 + h], pd0);
            atomicAdd(&d_as[row1 * 4 + h], ps1);
            atomicAdd(&d_ad[row1 * 4 + h], pd1);
        }
    }
}

// ---------------- edge head: BN2 stats + barrier + split-K x8 GEMM ----------
__global__ void __launch_bounds__(256) k_gemm_out(const float* __restrict__ A,
                                                  const float* __restrict__ B,
                                                  const int* __restrict__ mask,
                                                  float* __restrict__ out,
                                                  const float* __restrict__ g,
                                                  const float* __restrict__ b) {
    const int Nc = OUT_E;
    __shared__ float As[16][64];
    __shared__ float Bs[16][64];
    __shared__ int s_last;
    int tid = threadIdx.x;
    int bm = blockIdx.y * 64;
    int kbase = blockIdx.x * 64;
    int nblocks = gridDim.x * gridDim.y;             // 320
    int lb = blockIdx.y * gridDim.x + blockIdx.x;    // 0..319
    int tx = tid & 15, ty = tid >> 4;
    int ar = tid >> 2, ac = (tid & 3) << 2;
    int br = tid >> 4, bc = (tid & 15) << 2;

    // ---- BN2 partial stats: rows lb*8..+7, channels tid, tid+256 ----
    {
        int r0 = lb * 8;
        float s0 = 0.0f, q0 = 0.0f, s1 = 0.0f, q1 = 0.0f;
#pragma unroll
        for (int r = 0; r < 8; r++) {
            float v0 = d_agg[(size_t)(r0 + r) * F_HID + tid];
            float v1 = d_agg[(size_t)(r0 + r) * F_HID + tid + 256];
            s0 += v0; q0 += v0 * v0;
            s1 += v1; q1 += v1 * v1;
        }
        atomicAdd(&d_bnsum[tid], s0);
        atomicAdd(&d_bnsq[tid], q0);
        atomicAdd(&d_bnsum[tid + 256], s1);
        atomicAdd(&d_bnsq[tid + 256], q1);
    }
    __threadfence();
    __syncthreads();
    if (tid == 0) s_last = (atomicAdd(&d_ticket, 1) == nblocks - 1);
    __syncthreads();
    if (s_last) {
        for (int c = tid; c < F_HID; c += 256) {
            float mean = d_bnsum[c] * (1.0f / N_NODES);
            float var  = d_bnsq[c] * (1.0f / N_NODES) - mean * mean;
            float sc = rsqrtf(var + EPS_BN) * g[c];
            d_scale[c] = sc;
            d_shift[c] = b[c] - mean * sc;
            d_bnsum[c] = 0.0f;
            d_bnsq[c] = 0.0f;
        }
        __threadfence();
        __syncthreads();
        if (tid == 0) { d_ticket = 0; atomicExch(&d_flag2, 1); }
    }
    if (tid == 0) {
        while (atomicAdd(&d_flag2, 0) == 0) __nanosleep(64);
    }
    __syncthreads();
    __threadfence();

    float acc[4][4] = {};
    for (int k0 = kbase; k0 < kbase + 64; k0 += 16) {
        float4 av = *(const float4*)(A + (size_t)(bm + ar) * F_HID + k0 + ac);
        float4 sc = *(const float4*)(d_scale + k0 + ac);
        float4 sh = *(const float4*)(d_shift + k0 + ac);
        As[ac + 0][ar] = fmaxf(av.x * sc.x + sh.x, 0.0f);
        As[ac + 1][ar] = fmaxf(av.y * sc.y + sh.y, 0.0f);
        As[ac + 2][ar] = fmaxf(av.z * sc.z + sh.z, 0.0f);
        As[ac + 3][ar] = fmaxf(av.w * sc.w + sh.w, 0.0f);
        const float* Bp = B + (size_t)(k0 + br) * Nc;
        float4 bv;
        if (bc + 3 < Nc) bv = *(const float4*)(Bp + bc);
        else {
            bv.x = (bc + 0 < Nc) ? Bp[bc + 0] : 0.0f;
            bv.y = (bc + 1 < Nc) ? Bp[bc + 1] : 0.0f;
            bv.z = (bc + 2 < Nc) ? Bp[bc + 2] : 0.0f;
            bv.w = (bc + 3 < Nc) ? Bp[bc + 3] : 0.0f;
        }
        *(float4*)&Bs[br][bc] = bv;
        __syncthreads();
#pragma unroll
        for (int k = 0; k < 16; k++) {
            float a[4], bb[4];
#pragma unroll
            for (int i = 0; i < 4; i++) a[i] = As[k][(ty << 2) + i];
#pragma unroll
            for (int j = 0; j < 4; j++) bb[j] = Bs[k][(tx << 2) + j];
#pragma unroll
            for (int i = 0; i < 4; i++)
#pragma unroll
                for (int j = 0; j < 4; j++) acc[i][j] += a[i] * bb[j];
        }
        __syncthreads();
    }

#pragma unroll
    for (int i = 0; i < 4; i++) {
        int row = bm + (ty << 2) + i;
        float mk = (float)mask[row];
#pragma unroll
        for (int j = 0; j < 4; j++) {
            int col = (tx << 2) + j;
            if (col < Nc)
                atomicAdd(&out[(size_t)row * Nc + col], acc[i][j] * mk);
        }
    }
}

// ---------------- aggregation: 2 nodes/block, 64 thr/node, LDG.128 gather ---
__global__ void __launch_bounds__(128) k_aggregate(const float* __restrict__ bias, int layer) {
    __shared__ int   s_off[2][CAP];
    __shared__ float s_a[2][4][CAP];
    __shared__ float s_m[2][4];
    __shared__ float s_adc[2][4];
    __shared__ float s_cf[4];
    int tid = threadIdx.x;
    int half = tid >> 6, t = tid & 63;
    int n = (blockIdx.x << 1) + half;
    int h = t >> 4;
    int sub = t & 15;
    if (t < 4) s_adc[half][t] = d_ad[n * 4 + t];
    if (tid < 4) s_cf[tid] = d_coef[layer * 4 + tid];
    __syncthreads();
    int deg = min(d_cursor[n << 5], CAP);
    int off = n * CAP;

    for (int i = t; i < deg; i += 64) {
        int s = d_csr_src[off + i];
        float ew = d_csr_ew[off + i];
        s_off[half][i] = s * (F_HID * 2);
        float4 a4 = *(const float4*)&d_as[s * 4];
        float l0 = a4.x + s_adc[half][0] + ew * s_cf[0];
        float l1 = a4.y + s_adc[half][1] + ew * s_cf[1];
        float l2 = a4.z + s_adc[half][2] + ew * s_cf[2];
        float l3 = a4.w + s_adc[half][3] + ew * s_cf[3];
        s_a[half][0][i] = (l0 > 0.0f) ? l0 : 0.2f * l0;
        s_a[half][1][i] = (l1 > 0.0f) ? l1 : 0.2f * l1;
        s_a[half][2][i] = (l2 > 0.0f) ? l2 : 0.2f * l2;
        s_a[half][3][i] = (l3 > 0.0f) ? l3 : 0.2f * l3;
    }
    __syncthreads();

    float v = -1e30f;
    for (int i = sub; i < deg; i += 16) v = fmaxf(v, s_a[half][h][i]);
#pragma unroll
    for (int o = 8; o; o >>= 1) v = fmaxf(v, __shfl_xor_sync(0xffffffffu, v, o));
    if (sub == 0) s_m[half][h] = v;
    __syncthreads();

    for (int i = t; i < deg; i += 64) {
#pragma unroll
        for (int q = 0; q < 4; q++)
            s_a[half][q][i] = __expf(s_a[half][q][i] - s_m[half][q]);
    }
    __syncthreads();

    float rs = 0.0f;
    for (int i = sub; i < deg; i += 16) rs += s_a[half][h][i];
#pragma unroll
    for (int o = 8; o; o >>= 1) rs += __shfl_xor_sync(0xffffffffu, rs, o);

    const char* hb = (const char*)d_h + (t << 4);
    float acc[8] = {};
    int i = 0;
    for (; i + 4 <= deg; i += 4) {
        float4 wv = *(const float4*)&s_a[half][h][i];
        uint4 r0 = *(const uint4*)(hb + s_off[half][i]);
        uint4 r1 = *(const uint4*)(hb + s_off[half][i + 1]);
        uint4 r2 = *(const uint4*)(hb + s_off[half][i + 2]);
        uint4 r3 = *(const uint4*)(hb + s_off[half][i + 3]);
#pragma unroll
        for (int q = 0; q < 4; q++) {
            float2 f0 = __half22float2(*(__half2*)(&(&r0.x)[q]));
            float2 f1 = __half22float2(*(__half2*)(&(&r1.x)[q]));
            float2 f2 = __half22float2(*(__half2*)(&(&r2.x)[q]));
            float2 f3 = __half22float2(*(__half2*)(&(&r3.x)[q]));
            acc[q * 2 + 0] += wv.x * f0.x + wv.y * f1.x + wv.z * f2.x + wv.w * f3.x;
            acc[q * 2 + 1] += wv.x * f0.y + wv.y * f1.y + wv.z * f2.y + wv.w * f3.y;
        }
    }
    for (; i < deg; i++) {
        float wt = s_a[half][h][i];
        uint4 r = *(const uint4*)(hb + s_off[half][i]);
#pragma unroll
        for (int q = 0; q < 4; q++) {
            float2 f = __half22float2(*(__half2*)(&(&r.x)[q]));
            acc[q * 2 + 0] += wt * f.x;
            acc[q * 2 + 1] += wt * f.y;
        }
    }

    float inv = __fdividef(1.0f, rs + 1e-16f);
    float4 b0 = *(const float4*)(bias + (t << 3));
    float4 b1 = *(const float4*)(bias + (t << 3) + 4);
    float4 o0, o1;
    o0.x = acc[0] * inv + b0.x; o0.y = acc[1] * inv + b0.y;
    o0.z = acc[2] * inv + b0.z; o0.w = acc[3] * inv + b0.w;
    o1.x = acc[4] * inv + b1.x; o1.y = acc[5] * inv + b1.y;
    o1.z = acc[6] * inv + b1.z; o1.w = acc[7] * inv + b1.w;
    float* op = d_agg + (size_t)n * F_HID + (t << 3);
    *(float4*)(op) = o0;
    *(float4*)(op + 4) = o1;
}

// ---------------- launcher ----------------------------------------------------
extern "C" void kernel_launch(void* const* d_in, const int* in_sizes, int n_in,
                              void* d_out, int out_size) {
    const float* x    = (const float*)d_in[0];
    const int*   ei   = (const int*)d_in[1];
    const float* pos  = (const float*)d_in[2];
    const int*   mask = (const int*)d_in[3];
    const float* adj  = (const float*)d_in[4];
    const float* W1   = (const float*)d_in[5];
    const float* as1  = (const float*)d_in[6];
    const float* ad1  = (const float*)d_in[7];
    const float* We1  = (const float*)d_in[8];
    const float* ae1  = (const float*)d_in[9];
    const float* b1   = (const float*)d_in[10];
    const float* g1   = (const float*)d_in[11];
    const float* be1  = (const float*)d_in[12];
    const float* W2   = (const float*)d_in[13];
    const float* as2  = (const float*)d_in[14];
    const float* ad2  = (const float*)d_in[15];
    const float* We2  = (const float*)d_in[16];
    const float* ae2  = (const float*)d_in[17];
    const float* b2   = (const float*)d_in[18];
    const float* g2   = (const float*)d_in[19];
    const float* be2  = (const float*)d_in[20];
    const float* Wfc  = (const float*)d_in[21];
    const float* bfc  = (const float*)d_in[22];
    float* out = (float*)d_out;

    float *pagg;
    cudaGetSymbolAddress((void**)&pagg, d_agg);

    // preprocessing (convW + out-init + coef + zeroing + flags, one kernel)
    k_prep<<<128, 256>>>(W2, adj, bfc, mask, out, We1, ae1, We2, ae2);

    // fill (640 blocks) + GEMM1 (320 blocks) fused in one launch
    k_fill_gemm1<<<960, 256>>>(ei, pos, x, W1, as1, ad1);

    // ---- layer 1 ----
    k_aggregate<<<N_NODES / 2, 128>>>(b1, 0);

    // ---- layer 2: BN1 stats + barrier + HMMA (64x32 tiles, 640 blocks) ----
    k_gemm2_mma<<<dim3(F_HID / 32, N_NODES / 64), 256>>>(pagg, as2, ad2, g1, be1);
    k_aggregate<<<N_NODES / 2, 128>>>(b2, 1);

    // ---- edge head: BN2 stats + barrier + split-K x8 GEMM ----
    k_gemm_out<<<dim3(8, N_NODES / 64), 256>>>(pagg, Wfc, mask, out, g2, be2);
}

// round 15
// speedup vs baseline: 1.1252x; 1.1252x over previous
#include <cuda_runtime.h>
#include <cuda_fp16.h>
#include <math.h>

#define N_NODES 2560
#define N_EDGES 163840
#define HEADS   4
#define IN_C    32
#define C_HID   128
#define F_HID   512
#define OUT_E   40
#define EPS_BN  1e-5f
#define CAP     192

// ---------------- scratch (device globals) ----------------------------------
__device__ __half d_h[N_NODES * F_HID];
__device__ __half d_W2h[F_HID * F_HID];
__device__ float d_agg[N_NODES * F_HID];
__device__ __align__(16) float d_as[N_NODES * HEADS];
__device__ __align__(16) float d_ad[N_NODES * HEADS];
__device__ int   d_cursor[N_NODES * 32];
__device__ int   d_csr_src[N_NODES * CAP];
__device__ float d_csr_ew[N_NODES * CAP];
__device__ float d_coef[2 * HEADS];
__device__ float d_bnsum[F_HID];
__device__ float d_bnsq[F_HID];
__device__ int   d_ticket;
__device__ int   d_flag1;
__device__ int   d_flag2;
__device__ __align__(16) float d_scale[F_HID];
__device__ __align__(16) float d_shift[F_HID];

__device__ __forceinline__ unsigned smem_u32(const void* p) {
    return (unsigned)__cvta_generic_to_shared(p);
}

// ---------------- prep: convW + out-init + coef + zeroing (128 blocks) ------
__global__ void __launch_bounds__(256) k_prep(const float* __restrict__ W2,
                                              const float* __restrict__ adj,
                                              const float* __restrict__ bfc,
                                              const int* __restrict__ mask,
                                              float* __restrict__ out,
                                              const float* __restrict__ We1,
                                              const float* __restrict__ ae1,
                                              const float* __restrict__ We2,
                                              const float* __restrict__ ae2) {
    int gt = blockIdx.x * blockDim.x + threadIdx.x;   // 0..32767
    {
        int i = gt * 8;
        float4 f0 = *(const float4*)(W2 + i);
        float4 f1 = *(const float4*)(W2 + i + 4);
        __half2 h0 = __floats2half2_rn(f0.x, f0.y);
        __half2 h1 = __floats2half2_rn(f0.z, f0.w);
        __half2 h2 = __floats2half2_rn(f1.x, f1.y);
        __half2 h3 = __floats2half2_rn(f1.z, f1.w);
        uint4 pk;
        pk.x = *(unsigned*)&h0; pk.y = *(unsigned*)&h1;
        pk.z = *(unsigned*)&h2; pk.w = *(unsigned*)&h3;
        *(uint4*)(d_W2h + i) = pk;
    }
    for (int i = gt; i < N_NODES * OUT_E; i += 32768) {
        int n = i / OUT_E;
        int j = i - n * OUT_E;
        out[i] = adj[i] + bfc[j] * (float)mask[n];
    }
    if (gt < N_NODES) d_cursor[gt << 5] = 0;
    if (gt < N_NODES * HEADS) { d_as[gt] = 0.0f; d_ad[gt] = 0.0f; }
    if (gt < F_HID) { d_bnsum[gt] = 0.0f; d_bnsq[gt] = 0.0f; }
    if (gt == 0) { d_ticket = 0; d_flag1 = 0; d_flag2 = 0; }
    if (blockIdx.x == 0) {
        int w = threadIdx.x >> 5;
        int lane = threadIdx.x & 31;
        const float* We = (w < 4) ? We1 : We2;
        const float* ae = (w < 4) ? ae1 : ae2;
        int h = w & 3;
        float s = 0.0f;
        for (int i = lane; i < C_HID; i += 32) s += We[h * C_HID + i] * ae[h * C_HID + i];
#pragma unroll
        for (int o = 16; o; o >>= 1) s += __shfl_down_sync(0xffffffffu, s, o);
        if (lane == 0) d_coef[w] = s;
    }
}

// ---------------- fused: fill buckets (blocks 0..639) + GEMM1 (640..959) ----
__global__ void __launch_bounds__(256) k_fill_gemm1(const int* __restrict__ ei,
                                                    const float* __restrict__ pos,
                                                    const float* __restrict__ A,
                                                    const float* __restrict__ B,
                                                    const float* __restrict__ att_s,
                                                    const float* __restrict__ att_d) {
    if (blockIdx.x < 640) {
        int e = blockIdx.x * 256 + threadIdx.x;
        if (e >= N_EDGES) return;
        int s = ei[e], d = ei[N_EDGES + e];
        float dx = pos[2 * s] - pos[2 * d];
        float dy = pos[2 * s + 1] - pos[2 * d + 1];
        float ew = 1.0f / (sqrtf(dx * dx + dy * dy) + 1e-6f);
        int p = atomicAdd(&d_cursor[d << 5], 1);
        if (p < CAP) {
            d_csr_src[d * CAP + p] = s;
            d_csr_ew[d * CAP + p] = ew;
        }
        return;
    }
    // ---- GEMM1: 64x64 tile, K=32, attdot epilogue ----
    const int Nc = F_HID, K = IN_C;
    __shared__ float As[16][64];
    __shared__ float Bs[16][64];
    int blk = blockIdx.x - 640;          // 0..319
    int bm = (blk >> 3) * 64, bn = (blk & 7) * 64;
    int tid = threadIdx.x;
    int tx = tid & 15, ty = tid >> 4;
    int ar = tid >> 2, ac = (tid & 3) << 2;
    int br = tid >> 4, bc = (tid & 15) << 2;
    float acc[4][4] = {};

    for (int k0 = 0; k0 < K; k0 += 16) {
        float4 av = *(const float4*)(A + (size_t)(bm + ar) * K + k0 + ac);
        As[ac + 0][ar] = av.x; As[ac + 1][ar] = av.y;
        As[ac + 2][ar] = av.z; As[ac + 3][ar] = av.w;
        *(float4*)&Bs[br][bc] = *(const float4*)(B + (size_t)(k0 + br) * Nc + bn + bc);
        __syncthreads();
#pragma unroll
        for (int k = 0; k < 16; k++) {
            float a[4], b[4];
#pragma unroll
            for (int i = 0; i < 4; i++) a[i] = As[k][(ty << 2) + i];
#pragma unroll
            for (int j = 0; j < 4; j++) b[j] = Bs[k][(tx << 2) + j];
#pragma unroll
            for (int i = 0; i < 4; i++)
#pragma unroll
                for (int j = 0; j < 4; j++) acc[i][j] += a[i] * b[j];
        }
        __syncthreads();
    }

    int h = bn >> 7;
    int colbase = (bn & 127) + (tx << 2);
    float4 asv = *(const float4*)(att_s + h * C_HID + colbase);
    float4 adv = *(const float4*)(att_d + h * C_HID + colbase);
#pragma unroll
    for (int i = 0; i < 4; i++) {
        int row = bm + (ty << 2) + i;
        __half2 p0 = __floats2half2_rn(acc[i][0], acc[i][1]);
        __half2 p1 = __floats2half2_rn(acc[i][2], acc[i][3]);
        uint2 pk;
        pk.x = *(unsigned*)&p0;
        pk.y = *(unsigned*)&p1;
        *(uint2*)(d_h + (size_t)row * F_HID + bn + (tx << 2)) = pk;
        float ps = acc[i][0] * asv.x + acc[i][1] * asv.y + acc[i][2] * asv.z + acc[i][3] * asv.w;
        float pd = acc[i][0] * adv.x + acc[i][1] * adv.y + acc[i][2] * adv.z + acc[i][3] * adv.w;
#pragma unroll
        for (int o = 8; o; o >>= 1) {
            ps += __shfl_xor_sync(0xffffffffu, ps, o);
            pd += __shfl_xor_sync(0xffffffffu, pd, o);
        }
        if (tx == 0) {
            atomicAdd(&d_as[row * 4 + h], ps);
            atomicAdd(&d_ad[row * 4 + h], pd);
        }
    }
}

// ---------------- GEMM2: fused BN1 stats + barrier + 64x64 ping-pong HMMA ---
#define APAD 72
__global__ void __launch_bounds__(256) k_gemm2_mma(const float* __restrict__ A,
                                                   const float* __restrict__ att_s,
                                                   const float* __restrict__ att_d,
                                                   const float* __restrict__ g,
                                                   const float* __restrict__ b) {
    __shared__ __half As[2][64 * APAD];
    __shared__ __half Bs[2][64 * APAD];
    __shared__ float s_sc[F_HID];
    __shared__ float s_sh[F_HID];
    __shared__ int s_last;
    int tid = threadIdx.x;
    int lane = tid & 31, wid = tid >> 5;
    int warp_m = wid >> 1, warp_n = wid & 1;
    int bm = blockIdx.y * 64, bn = blockIdx.x * 64;
    int nblocks = gridDim.x * gridDim.y;                 // 320
    int lb = blockIdx.y * gridDim.x + blockIdx.x;        // 0..319

    int arow = tid >> 2, aseg = (tid & 3) * 16;
    int brow = tid >> 2, bseg = (tid & 3) * 8;

    // prefetch tile 0 (independent of BN) — overlaps the barrier below
    float4 aReg[4];
    uint4  bReg[2];
    {
        const float* Ap = A + (size_t)(bm + arow) * F_HID + aseg;
#pragma unroll
        for (int j = 0; j < 4; j++) aReg[j] = *(const float4*)(Ap + j * 4);
#pragma unroll
        for (int j = 0; j < 2; j++)
            bReg[j] = *(const uint4*)(d_W2h + (size_t)brow * F_HID + bn + bseg + j * 32);
    }

    // ---- BN1 partial stats: rows lb*8..lb*8+7, channels tid and tid+256 ----
    {
        int r0 = lb * 8;
        float s0 = 0.0f, q0 = 0.0f, s1 = 0.0f, q1 = 0.0f;
#pragma unroll
        for (int r = 0; r < 8; r++) {
            float v0 = d_agg[(size_t)(r0 + r) * F_HID + tid];
            float v1 = d_agg[(size_t)(r0 + r) * F_HID + tid + 256];
            s0 += v0; q0 += v0 * v0;
            s1 += v1; q1 += v1 * v1;
        }
        atomicAdd(&d_bnsum[tid], s0);
        atomicAdd(&d_bnsq[tid], q0);
        atomicAdd(&d_bnsum[tid + 256], s1);
        atomicAdd(&d_bnsq[tid + 256], q1);
    }
    __threadfence();
    __syncthreads();
    if (tid == 0) s_last = (atomicAdd(&d_ticket, 1) == nblocks - 1);
    __syncthreads();
    if (s_last) {
        for (int c = tid; c < F_HID; c += 256) {
            float mean = d_bnsum[c] * (1.0f / N_NODES);
            float var  = d_bnsq[c] * (1.0f / N_NODES) - mean * mean;
            float sc = rsqrtf(var + EPS_BN) * g[c];
            d_scale[c] = sc;
            d_shift[c] = b[c] - mean * sc;
            d_bnsum[c] = 0.0f;
            d_bnsq[c] = 0.0f;
        }
        for (int i = tid; i < N_NODES * HEADS; i += 256) {
            d_as[i] = 0.0f;
            d_ad[i] = 0.0f;
        }
        __threadfence();
        __syncthreads();
        if (tid == 0) { d_ticket = 0; atomicExch(&d_flag1, 1); }
    }
    if (tid == 0) {
        while (atomicAdd(&d_flag1, 0) == 0) __nanosleep(64);
    }
    __syncthreads();
    __threadfence();

    // load scale/shift to smem
    for (int i = tid; i < F_HID; i += 256) {
        s_sc[i] = d_scale[i];
        s_sh[i] = d_shift[i];
    }
    __syncthreads();

    float acc[4][4] = {};
    // store tile 0 (BN + cvt)
    {
        int cb = aseg;
#pragma unroll
        for (int j = 0; j < 4; j++) {
            float4 f = aReg[j];
            float4 sc = *(const float4*)(s_sc + cb + j * 4);
            float4 sh = *(const float4*)(s_sh + cb + j * 4);
            f.x = fmaxf(f.x * sc.x + sh.x, 0.0f);
            f.y = fmaxf(f.y * sc.y + sh.y, 0.0f);
            f.z = fmaxf(f.z * sc.z + sh.z, 0.0f);
            f.w = fmaxf(f.w * sc.w + sh.w, 0.0f);
            __half2 h0 = __floats2half2_rn(f.x, f.y);
            __half2 h1 = __floats2half2_rn(f.z, f.w);
            uint2 pk; pk.x = *(unsigned*)&h0; pk.y = *(unsigned*)&h1;
            *(uint2*)(As[0] + arow * APAD + aseg + j * 4) = pk;
        }
#pragma unroll
        for (int j = 0; j < 2; j++)
            *(uint4*)(Bs[0] + brow * APAD + bseg + j * 32) = bReg[j];
    }
    __syncthreads();

    for (int kt = 0; kt < 8; kt++) {
        int cur = kt & 1, nxt = cur ^ 1;
        if (kt < 7) {
            int k0n = (kt + 1) * 64;
            const float* Ap = A + (size_t)(bm + arow) * F_HID + k0n + aseg;
#pragma unroll
            for (int j = 0; j < 4; j++) aReg[j] = *(const float4*)(Ap + j * 4);
#pragma unroll
            for (int j = 0; j < 2; j++)
                bReg[j] = *(const uint4*)(d_W2h + (size_t)(k0n + brow) * F_HID + bn + bseg + j * 32);
        }

#pragma unroll
        for (int kk = 0; kk < 64; kk += 16) {
            unsigned aF[4], bF[2][4];
            {
                unsigned addr = smem_u32(As[cur] + (warp_m * 16 + (lane & 15)) * APAD
                                            + kk + ((lane >> 4) << 3));
                asm volatile("ldmatrix.sync.aligned.m8n8.x4.shared.b16 {%0,%1,%2,%3}, [%4];"
                             : "=r"(aF[0]), "=r"(aF[1]), "=r"(aF[2]), "=r"(aF[3])
                             : "r"(addr));
            }
#pragma unroll
            for (int nj = 0; nj < 2; nj++) {
                unsigned addr = smem_u32(Bs[cur] + (kk + (lane & 15)) * APAD
                                            + warp_n * 32 + nj * 16 + ((lane >> 4) << 3));
                asm volatile("ldmatrix.sync.aligned.m8n8.x4.trans.shared.b16 {%0,%1,%2,%3}, [%4];"
                             : "=r"(bF[nj][0]), "=r"(bF[nj][1]), "=r"(bF[nj][2]), "=r"(bF[nj][3])
                             : "r"(addr));
            }
#pragma unroll
            for (int ni = 0; ni < 4; ni++) {
                unsigned b0 = bF[ni >> 1][(ni & 1) * 2];
                unsigned b1 = bF[ni >> 1][(ni & 1) * 2 + 1];
                asm volatile(
                    "mma.sync.aligned.m16n8k16.row.col.f32.f16.f16.f32 "
                    "{%0,%1,%2,%3}, {%4,%5,%6,%7}, {%8,%9}, {%0,%1,%2,%3};"
                    : "+f"(acc[ni][0]), "+f"(acc[ni][1]),
                      "+f"(acc[ni][2]), "+f"(acc[ni][3])
                    : "r"(aF[0]), "r"(aF[1]), "r"(aF[2]), "r"(aF[3]),
                      "r"(b0), "r"(b1));
            }
        }

        if (kt < 7) {
            int cb = (kt + 1) * 64 + aseg;
#pragma unroll
            for (int j = 0; j < 4; j++) {
                float4 f = aReg[j];
                float4 sc = *(const float4*)(s_sc + cb + j * 4);
                float4 sh = *(const float4*)(s_sh + cb + j * 4);
                f.x = fmaxf(f.x * sc.x + sh.x, 0.0f);
                f.y = fmaxf(f.y * sc.y + sh.y, 0.0f);
                f.z = fmaxf(f.z * sc.z + sh.z, 0.0f);
                f.w = fmaxf(f.w * sc.w + sh.w, 0.0f);
                __half2 h0 = __floats2half2_rn(f.x, f.y);
                __half2 h1 = __floats2half2_rn(f.z, f.w);
                uint2 pk; pk.x = *(unsigned*)&h0; pk.y = *(unsigned*)&h1;
                *(uint2*)(As[nxt] + arow * APAD + aseg + j * 4) = pk;
            }
#pragma unroll
            for (int j = 0; j < 2; j++)
                *(uint4*)(Bs[nxt] + brow * APAD + bseg + j * 32) = bReg[j];
            __syncthreads();
        }
    }

    // epilogue: fp16 store + attention dot partials
    int h = bn >> 7;
    int colh = (bn & 127) + warp_n * 32;
    float asv[4][2], adv[4][2];
#pragma unroll
    for (int ni = 0; ni < 4; ni++) {
        int c0 = colh + ni * 8 + (lane & 3) * 2;
        asv[ni][0] = att_s[h * C_HID + c0];
        asv[ni][1] = att_s[h * C_HID + c0 + 1];
        adv[ni][0] = att_d[h * C_HID + c0];
        adv[ni][1] = att_d[h * C_HID + c0 + 1];
    }
    {
        int row0 = bm + warp_m * 16 + (lane >> 2);
        int row1 = row0 + 8;
        float ps0 = 0.0f, pd0 = 0.0f, ps1 = 0.0f, pd1 = 0.0f;
#pragma unroll
        for (int ni = 0; ni < 4; ni++) {
            int col = bn + warp_n * 32 + ni * 8 + (lane & 3) * 2;
            __half2 h0 = __floats2half2_rn(acc[ni][0], acc[ni][1]);
            __half2 h1 = __floats2half2_rn(acc[ni][2], acc[ni][3]);
            *(__half2*)(d_h + (size_t)row0 * F_HID + col) = h0;
            *(__half2*)(d_h + (size_t)row1 * F_HID + col) = h1;
            ps0 += acc[ni][0] * asv[ni][0] + acc[ni][1] * asv[ni][1];
            ps1 += acc[ni][2] * asv[ni][0] + acc[ni][3] * asv[ni][1];
            pd0 += acc[ni][0] * adv[ni][0] + acc[ni][1] * adv[ni][1];
            pd1 += acc[ni][2] * adv[ni][0] + acc[ni][3] * adv[ni][1];
        }
#pragma unroll
        for (int o = 1; o < 4; o <<= 1) {
            ps0 += __shfl_xor_sync(0xffffffffu, ps0, o);
            ps1 += __shfl_xor_sync(0xffffffffu, ps1, o);
            pd0 += __shfl_xor_sync(0xffffffffu, pd0, o);
            pd1 += __shfl_xor_sync(0xffffffffu, pd1, o);
        }
        if ((lane & 3) == 0) {
            atomicAdd(&d_as[row0 * 4 + h], ps0);
            atomicAdd(&d_ad[row0 * 4 + h], pd0);
            atomicAdd(&d_as[row1 * 4 + h], ps1);
            atomicAdd(&d_ad[row1 * 4 + h], pd1);
        }
    }
}

// ---------------- edge head: fused BN2 stats + barrier + split-K x4 GEMM ----
__global__ void __launch_bounds__(256) k_gemm_out(const float* __restrict__ A,
                                                  const float* __restrict__ B,
                                                  const int* __restrict__ mask,
                                                  float* __restrict__ out,
                                                  const float* __restrict__ g,
                                                  const float* __restrict__ b) {
    const int Nc = OUT_E;
    __shared__ float As[16][64];
    __shared__ float Bs[16][64];
    __shared__ int s_last;
    int tid = threadIdx.x;
    int bm = blockIdx.y * 64;
    int kbase = blockIdx.x * 128;
    int nblocks = gridDim.x * gridDim.y;             // 160
    int lb = blockIdx.y * gridDim.x + blockIdx.x;    // 0..159
    int tx = tid & 15, ty = tid >> 4;
    int ar = tid >> 2, ac = (tid & 3) << 2;
    int br = tid >> 4, bc = (tid & 15) << 2;

    // ---- BN2 partial stats: rows lb*16..+15, channels tid, tid+256 ----
    {
        int r0 = lb * 16;
        float s0 = 0.0f, q0 = 0.0f, s1 = 0.0f, q1 = 0.0f;
#pragma unroll
        for (int r = 0; r < 16; r++) {
            float v0 = d_agg[(size_t)(r0 + r) * F_HID + tid];
            float v1 = d_agg[(size_t)(r0 + r) * F_HID + tid + 256];
            s0 += v0; q0 += v0 * v0;
            s1 += v1; q1 += v1 * v1;
        }
        atomicAdd(&d_bnsum[tid], s0);
        atomicAdd(&d_bnsq[tid], q0);
        atomicAdd(&d_bnsum[tid + 256], s1);
        atomicAdd(&d_bnsq[tid + 256], q1);
    }
    __threadfence();
    __syncthreads();
    if (tid == 0) s_last = (atomicAdd(&d_ticket, 1) == nblocks - 1);
    __syncthreads();
    if (s_last) {
        for (int c = tid; c < F_HID; c += 256) {
            float mean = d_bnsum[c] * (1.0f / N_NODES);
            float var  = d_bnsq[c] * (1.0f / N_NODES) - mean * mean;
            float sc = rsqrtf(var + EPS_BN) * g[c];
            d_scale[c] = sc;
            d_shift[c] = b[c] - mean * sc;
            d_bnsum[c] = 0.0f;
            d_bnsq[c] = 0.0f;
        }
        __threadfence();
        __syncthreads();
        if (tid == 0) { d_ticket = 0; atomicExch(&d_flag2, 1); }
    }
    if (tid == 0) {
        while (atomicAdd(&d_flag2, 0) == 0) __nanosleep(64);
    }
    __syncthreads();
    __threadfence();

    float acc[4][4] = {};
    for (int k0 = kbase; k0 < kbase + 128; k0 += 16) {
        float4 av = *(const float4*)(A + (size_t)(bm + ar) * F_HID + k0 + ac);
        float4 sc = *(const float4*)(d_scale + k0 + ac);
        float4 sh = *(const float4*)(d_shift + k0 + ac);
        As[ac + 0][ar] = fmaxf(av.x * sc.x + sh.x, 0.0f);
        As[ac + 1][ar] = fmaxf(av.y * sc.y + sh.y, 0.0f);
        As[ac + 2][ar] = fmaxf(av.z * sc.z + sh.z, 0.0f);
        As[ac + 3][ar] = fmaxf(av.w * sc.w + sh.w, 0.0f);
        const float* Bp = B + (size_t)(k0 + br) * Nc;
        float4 bv;
        if (bc + 3 < Nc) bv = *(const float4*)(Bp + bc);
        else {
            bv.x = (bc + 0 < Nc) ? Bp[bc + 0] : 0.0f;
            bv.y = (bc + 1 < Nc) ? Bp[bc + 1] : 0.0f;
            bv.z = (bc + 2 < Nc) ? Bp[bc + 2] : 0.0f;
            bv.w = (bc + 3 < Nc) ? Bp[bc + 3] : 0.0f;
        }
        *(float4*)&Bs[br][bc] = bv;
        __syncthreads();
#pragma unroll
        for (int k = 0; k < 16; k++) {
            float a[4], bb[4];
#pragma unroll
            for (int i = 0; i < 4; i++) a[i] = As[k][(ty << 2) + i];
#pragma unroll
            for (int j = 0; j < 4; j++) bb[j] = Bs[k][(tx << 2) + j];
#pragma unroll
            for (int i = 0; i < 4; i++)
#pragma unroll
                for (int j = 0; j < 4; j++) acc[i][j] += a[i] * bb[j];
        }
        __syncthreads();
    }

#pragma unroll
    for (int i = 0; i < 4; i++) {
        int row = bm + (ty << 2) + i;
        float mk = (float)mask[row];
#pragma unroll
        for (int j = 0; j < 4; j++) {
            int col = (tx << 2) + j;
            if (col < Nc)
                atomicAdd(&out[(size_t)row * Nc + col], acc[i][j] * mk);
        }
    }
}

// ---------------- aggregation: 2 nodes/block, 64 thr/node, fused exp+sum ----
__global__ void __launch_bounds__(128) k_aggregate(const float* __restrict__ bias, int layer) {
    __shared__ int   s_off[2][CAP];
    __shared__ float s_a[2][4][CAP];
    __shared__ float s_adc[2][4];
    __shared__ float s_cf[4];
    int tid = threadIdx.x;
    int half = tid >> 6, t = tid & 63;
    int n = (blockIdx.x << 1) + half;
    int h = t >> 4;
    int sub = t & 15;
    if (t < 4) s_adc[half][t] = d_ad[n * 4 + t];
    if (tid < 4) s_cf[tid] = d_coef[layer * 4 + tid];
    __syncthreads();
    int deg = min(d_cursor[n << 5], CAP);
    int off = n * CAP;

    for (int i = t; i < deg; i += 64) {
        int s = d_csr_src[off + i];
        float ew = d_csr_ew[off + i];
        s_off[half][i] = s * (F_HID * 2);
        float4 a4 = *(const float4*)&d_as[s * 4];
        float l0 = a4.x + s_adc[half][0] + ew * s_cf[0];
        float l1 = a4.y + s_adc[half][1] + ew * s_cf[1];
        float l2 = a4.z + s_adc[half][2] + ew * s_cf[2];
        float l3 = a4.w + s_adc[half][3] + ew * s_cf[3];
        s_a[half][0][i] = (l0 > 0.0f) ? l0 : 0.2f * l0;
        s_a[half][1][i] = (l1 > 0.0f) ? l1 : 0.2f * l1;
        s_a[half][2][i] = (l2 > 0.0f) ? l2 : 0.2f * l2;
        s_a[half][3][i] = (l3 > 0.0f) ? l3 : 0.2f * l3;
    }
    __syncthreads();

    // per-head max (each 16-lane group owns its head; all lanes end with max)
    float v = -1e30f;
    for (int i = sub; i < deg; i += 16) v = fmaxf(v, s_a[half][h][i]);
#pragma unroll
    for (int o = 8; o; o >>= 1) v = fmaxf(v, __shfl_xor_sync(0xffffffffu, v, o));

    // fused exp + sum for own head (writes/reads stay within this warp)
    float rs = 0.0f;
    for (int i = sub; i < deg; i += 16) {
        float e = __expf(s_a[half][h][i] - v);
        s_a[half][h][i] = e;
        rs += e;
    }
#pragma unroll
    for (int o = 8; o; o >>= 1) rs += __shfl_xor_sync(0xffffffffu, rs, o);
    __syncwarp();

    const char* hb = (const char*)d_h + (t << 4);
    float acc[8] = {};
    int i = 0;
    for (; i + 4 <= deg; i += 4) {
        float4 wv = *(const float4*)&s_a[half][h][i];
        uint4 r0 = *(const uint4*)(hb + s_off[half][i]);
        uint4 r1 = *(const uint4*)(hb + s_off[half][i + 1]);
        uint4 r2 = *(const uint4*)(hb + s_off[half][i + 2]);
        uint4 r3 = *(const uint4*)(hb + s_off[half][i + 3]);
#pragma unroll
        for (int q = 0; q < 4; q++) {
            float2 f0 = __half22float2(*(__half2*)(&(&r0.x)[q]));
            float2 f1 = __half22float2(*(__half2*)(&(&r1.x)[q]));
            float2 f2 = __half22float2(*(__half2*)(&(&r2.x)[q]));
            float2 f3 = __half22float2(*(__half2*)(&(&r3.x)[q]));
            acc[q * 2 + 0] += wv.x * f0.x + wv.y * f1.x + wv.z * f2.x + wv.w * f3.x;
            acc[q * 2 + 1] += wv.x * f0.y + wv.y * f1.y + wv.z * f2.y + wv.w * f3.y;
        }
    }
    for (; i < deg; i++) {
        float wt = s_a[half][h][i];
        uint4 r = *(const uint4*)(hb + s_off[half][i]);
#pragma unroll
        for (int q = 0; q < 4; q++) {
            float2 f = __half22float2(*(__half2*)(&(&r.x)[q]));
            acc[q * 2 + 0] += wt * f.x;
            acc[q * 2 + 1] += wt * f.y;
        }
    }

    float inv = __fdividef(1.0f, rs + 1e-16f);
    float4 b0 = *(const float4*)(bias + (t << 3));
    float4 b1 = *(const float4*)(bias + (t << 3) + 4);
    float4 o0, o1;
    o0.x = acc[0] * inv + b0.x; o0.y = acc[1] * inv + b0.y;
    o0.z = acc[2] * inv + b0.z; o0.w = acc[3] * inv + b0.w;
    o1.x = acc[4] * inv + b1.x; o1.y = acc[5] * inv + b1.y;
    o1.z = acc[6] * inv + b1.z; o1.w = acc[7] * inv + b1.w;
    float* op = d_agg + (size_t)n * F_HID + (t << 3);
    *(float4*)(op) = o0;
    *(float4*)(op + 4) = o1;
}

// ---------------- launcher ----------------------------------------------------
extern "C" void kernel_launch(void* const* d_in, const int* in_sizes, int n_in,
                              void* d_out, int out_size) {
    const float* x    = (const float*)d_in[0];
    const int*   ei   = (const int*)d_in[1];
    const float* pos  = (const float*)d_in[2];
    const int*   mask = (const int*)d_in[3];
    const float* adj  = (const float*)d_in[4];
    const float* W1   = (const float*)d_in[5];
    const float* as1  = (const float*)d_in[6];
    const float* ad1  = (const float*)d_in[7];
    const float* We1  = (const float*)d_in[8];
    const float* ae1  = (const float*)d_in[9];
    const float* b1   = (const float*)d_in[10];
    const float* g1   = (const float*)d_in[11];
    const float* be1  = (const float*)d_in[12];
    const float* W2   = (const float*)d_in[13];
    const float* as2  = (const float*)d_in[14];
    const float* ad2  = (const float*)d_in[15];
    const float* We2  = (const float*)d_in[16];
    const float* ae2  = (const float*)d_in[17];
    const float* b2   = (const float*)d_in[18];
    const float* g2   = (const float*)d_in[19];
    const float* be2  = (const float*)d_in[20];
    const float* Wfc  = (const float*)d_in[21];
    const float* bfc  = (const float*)d_in[22];
    float* out = (float*)d_out;

    float *pagg;
    cudaGetSymbolAddress((void**)&pagg, d_agg);

    // preprocessing (convW + out-init + coef + zeroing + flags, one kernel)
    k_prep<<<128, 256>>>(W2, adj, bfc, mask, out, We1, ae1, We2, ae2);

    // fill (640 blocks) + GEMM1 (320 blocks) fused in one launch
    k_fill_gemm1<<<960, 256>>>(ei, pos, x, W1, as1, ad1);

    // ---- layer 1 ----
    k_aggregate<<<N_NODES / 2, 128>>>(b1, 0);

    // ---- layer 2: BN1 stats + barrier + HMMA (64x64, 320 blocks) ----
    k_gemm2_mma<<<dim3(F_HID / 64, N_NODES / 64), 256>>>(pagg, as2, ad2, g1, be1);
    k_aggregate<<<N_NODES / 2, 128>>>(b2, 1);

    // ---- edge head: BN2 stats + barrier + split-K x4 GEMM ----
    k_gemm_out<<<dim3(4, N_NODES / 64), 256>>>(pagg, Wfc, mask, out, g2, be2);
}

// round 16
// speedup vs baseline: 1.1438x; 1.0165x over previous
#include <cuda_runtime.h>
#include <cuda_fp16.h>
#include <math.h>

#define N_NODES 2560
#define N_EDGES 163840
#define HEADS   4
#define IN_C    32
#define C_HID   128
#define F_HID   512
#define OUT_E   40
#define EPS_BN  1e-5f
#define CAP     192

// ---------------- scratch (device globals) ----------------------------------
__device__ __half d_h[N_NODES * F_HID];
__device__ __half d_W2h[F_HID * F_HID];
__device__ float d_agg[N_NODES * F_HID];
__device__ __align__(16) float d_as[N_NODES * HEADS];
__device__ __align__(16) float d_ad[N_NODES * HEADS];
__device__ int   d_cursor[N_NODES * 32];
__device__ int   d_csr_src[N_NODES * CAP];
__device__ float d_csr_ew[N_NODES * CAP];
__device__ float d_coef[2 * HEADS];
__device__ float d_bnsum[F_HID];
__device__ float d_bnsq[F_HID];
__device__ int   d_ticket;
__device__ int   d_flag1;
__device__ int   d_flag2;
__device__ __align__(16) float d_scale[F_HID];
__device__ __align__(16) float d_shift[F_HID];

__device__ __forceinline__ unsigned smem_u32(const void* p) {
    return (unsigned)__cvta_generic_to_shared(p);
}

// ---------------- prep: convW + out-init + coef + zeroing (128 blocks) ------
__global__ void __launch_bounds__(256) k_prep(const float* __restrict__ W2,
                                              const float* __restrict__ adj,
                                              const float* __restrict__ bfc,
                                              const int* __restrict__ mask,
                                              float* __restrict__ out,
                                              const float* __restrict__ We1,
                                              const float* __restrict__ ae1,
                                              const float* __restrict__ We2,
                                              const float* __restrict__ ae2) {
    int gt = blockIdx.x * blockDim.x + threadIdx.x;   // 0..32767
    {
        int i = gt * 8;
        float4 f0 = *(const float4*)(W2 + i);
        float4 f1 = *(const float4*)(W2 + i + 4);
        __half2 h0 = __floats2half2_rn(f0.x, f0.y);
        __half2 h1 = __floats2half2_rn(f0.z, f0.w);
        __half2 h2 = __floats2half2_rn(f1.x, f1.y);
        __half2 h3 = __floats2half2_rn(f1.z, f1.w);
        uint4 pk;
        pk.x = *(unsigned*)&h0; pk.y = *(unsigned*)&h1;
        pk.z = *(unsigned*)&h2; pk.w = *(unsigned*)&h3;
        *(uint4*)(d_W2h + i) = pk;
    }
    for (int i = gt; i < N_NODES * OUT_E; i += 32768) {
        int n = i / OUT_E;
        int j = i - n * OUT_E;
        out[i] = adj[i] + bfc[j] * (float)mask[n];
    }
    if (gt < N_NODES) d_cursor[gt << 5] = 0;
    if (gt < N_NODES * HEADS) { d_as[gt] = 0.0f; d_ad[gt] = 0.0f; }
    if (gt < F_HID) { d_bnsum[gt] = 0.0f; d_bnsq[gt] = 0.0f; }
    if (gt == 0) { d_ticket = 0; d_flag1 = 0; d_flag2 = 0; }
    if (blockIdx.x == 0) {
        int w = threadIdx.x >> 5;
        int lane = threadIdx.x & 31;
        const float* We = (w < 4) ? We1 : We2;
        const float* ae = (w < 4) ? ae1 : ae2;
        int h = w & 3;
        float s = 0.0f;
        for (int i = lane; i < C_HID; i += 32) s += We[h * C_HID + i] * ae[h * C_HID + i];
#pragma unroll
        for (int o = 16; o; o >>= 1) s += __shfl_down_sync(0xffffffffu, s, o);
        if (lane == 0) d_coef[w] = s;
    }
}

// ---------------- fused: fill buckets (blocks 0..639) + GEMM1 (640..959) ----
__global__ void __launch_bounds__(256) k_fill_gemm1(const int* __restrict__ ei,
                                                    const float* __restrict__ pos,
                                                    const float* __restrict__ A,
                                                    const float* __restrict__ B,
                                                    const float* __restrict__ att_s,
                                                    const float* __restrict__ att_d) {
    if (blockIdx.x < 640) {
        int e = blockIdx.x * 256 + threadIdx.x;
        if (e >= N_EDGES) return;
        int s = ei[e], d = ei[N_EDGES + e];
        float dx = pos[2 * s] - pos[2 * d];
        float dy = pos[2 * s + 1] - pos[2 * d + 1];
        float ew = 1.0f / (sqrtf(dx * dx + dy * dy) + 1e-6f);
        int p = atomicAdd(&d_cursor[d << 5], 1);
        if (p < CAP) {
            d_csr_src[d * CAP + p] = s;
            d_csr_ew[d * CAP + p] = ew;
        }
        return;
    }
    // ---- GEMM1: 64x64 tile, K=32, attdot epilogue ----
    const int Nc = F_HID, K = IN_C;
    __shared__ float As[16][64];
    __shared__ float Bs[16][64];
    int blk = blockIdx.x - 640;          // 0..319
    int bm = (blk >> 3) * 64, bn = (blk & 7) * 64;
    int tid = threadIdx.x;
    int tx = tid & 15, ty = tid >> 4;
    int ar = tid >> 2, ac = (tid & 3) << 2;
    int br = tid >> 4, bc = (tid & 15) << 2;
    float acc[4][4] = {};

    for (int k0 = 0; k0 < K; k0 += 16) {
        float4 av = *(const float4*)(A + (size_t)(bm + ar) * K + k0 + ac);
        As[ac + 0][ar] = av.x; As[ac + 1][ar] = av.y;
        As[ac + 2][ar] = av.z; As[ac + 3][ar] = av.w;
        *(float4*)&Bs[br][bc] = *(const float4*)(B + (size_t)(k0 + br) * Nc + bn + bc);
        __syncthreads();
#pragma unroll
        for (int k = 0; k < 16; k++) {
            float a[4], b[4];
#pragma unroll
            for (int i = 0; i < 4; i++) a[i] = As[k][(ty << 2) + i];
#pragma unroll
            for (int j = 0; j < 4; j++) b[j] = Bs[k][(tx << 2) + j];
#pragma unroll
            for (int i = 0; i < 4; i++)
#pragma unroll
                for (int j = 0; j < 4; j++) acc[i][j] += a[i] * b[j];
        }
        __syncthreads();
    }

    int h = bn >> 7;
    int colbase = (bn & 127) + (tx << 2);
    float4 asv = *(const float4*)(att_s + h * C_HID + colbase);
    float4 adv = *(const float4*)(att_d + h * C_HID + colbase);
#pragma unroll
    for (int i = 0; i < 4; i++) {
        int row = bm + (ty << 2) + i;
        __half2 p0 = __floats2half2_rn(acc[i][0], acc[i][1]);
        __half2 p1 = __floats2half2_rn(acc[i][2], acc[i][3]);
        uint2 pk;
        pk.x = *(unsigned*)&p0;
        pk.y = *(unsigned*)&p1;
        *(uint2*)(d_h + (size_t)row * F_HID + bn + (tx << 2)) = pk;
        float ps = acc[i][0] * asv.x + acc[i][1] * asv.y + acc[i][2] * asv.z + acc[i][3] * asv.w;
        float pd = acc[i][0] * adv.x + acc[i][1] * adv.y + acc[i][2] * adv.z + acc[i][3] * adv.w;
#pragma unroll
        for (int o = 8; o; o >>= 1) {
            ps += __shfl_xor_sync(0xffffffffu, ps, o);
            pd += __shfl_xor_sync(0xffffffffu, pd, o);
        }
        if (tx == 0) {
            atomicAdd(&d_as[row * 4 + h], ps);
            atomicAdd(&d_ad[row * 4 + h], pd);
        }
    }
}

// ---------------- GEMM2: BN1 stats + barrier + 32x64 M-split HMMA -----------
// grid (8, 80) = 640 blocks; each block 32 M-rows x 64 N-cols.
#define APAD 72
__global__ void __launch_bounds__(256) k_gemm2_mma(const float* __restrict__ A,
                                                   const float* __restrict__ att_s,
                                                   const float* __restrict__ att_d,
                                                   const float* __restrict__ g,
                                                   const float* __restrict__ b) {
    __shared__ __half As[2][32 * APAD];
    __shared__ __half Bs[2][64 * APAD];
    __shared__ float s_sc[F_HID];
    __shared__ float s_sh[F_HID];
    __shared__ int s_last;
    int tid = threadIdx.x;
    int lane = tid & 31, wid = tid >> 5;
    int warp_m = wid >> 2, warp_n = wid & 3;    // 2x4 warps, 16x16 per warp
    int bm = blockIdx.y * 32, bn = blockIdx.x * 64;
    int nblocks = gridDim.x * gridDim.y;                 // 640
    int lb = blockIdx.y * gridDim.x + blockIdx.x;        // 0..639

    int arow = tid >> 3, aseg = (tid & 7) * 8;   // A: 32 rows x 64 k, 8 floats/thr
    int brow = tid >> 2, bseg = (tid & 3) * 16;  // B: 64 k-rows x 64 n, 16 halfs/thr

    // prefetch tile 0 (independent of BN) — overlaps the barrier below
    float4 aReg[2];
    uint4  bReg[2];
    {
        const float* Ap = A + (size_t)(bm + arow) * F_HID + aseg;
        aReg[0] = *(const float4*)(Ap);
        aReg[1] = *(const float4*)(Ap + 4);
        bReg[0] = *(const uint4*)(d_W2h + (size_t)brow * F_HID + bn + bseg);
        bReg[1] = *(const uint4*)(d_W2h + (size_t)brow * F_HID + bn + bseg + 8);
    }

    // ---- BN1 partial stats: rows lb*4..+3, channels tid, tid+256 ----
    {
        int r0 = lb * 4;
        float s0 = 0.0f, q0 = 0.0f, s1 = 0.0f, q1 = 0.0f;
#pragma unroll
        for (int r = 0; r < 4; r++) {
            float v0 = d_agg[(size_t)(r0 + r) * F_HID + tid];
            float v1 = d_agg[(size_t)(r0 + r) * F_HID + tid + 256];
            s0 += v0; q0 += v0 * v0;
            s1 += v1; q1 += v1 * v1;
        }
        atomicAdd(&d_bnsum[tid], s0);
        atomicAdd(&d_bnsq[tid], q0);
        atomicAdd(&d_bnsum[tid + 256], s1);
        atomicAdd(&d_bnsq[tid + 256], q1);
    }
    __threadfence();
    __syncthreads();
    if (tid == 0) s_last = (atomicAdd(&d_ticket, 1) == nblocks - 1);
    __syncthreads();
    if (s_last) {
        for (int c = tid; c < F_HID; c += 256) {
            float mean = d_bnsum[c] * (1.0f / N_NODES);
            float var  = d_bnsq[c] * (1.0f / N_NODES) - mean * mean;
            float sc = rsqrtf(var + EPS_BN) * g[c];
            d_scale[c] = sc;
            d_shift[c] = b[c] - mean * sc;
            d_bnsum[c] = 0.0f;
            d_bnsq[c] = 0.0f;
        }
        for (int i = tid; i < N_NODES * HEADS; i += 256) {
            d_as[i] = 0.0f;
            d_ad[i] = 0.0f;
        }
        __threadfence();
        __syncthreads();
        if (tid == 0) { d_ticket = 0; atomicExch(&d_flag1, 1); }
    }
    if (tid == 0) {
        while (atomicAdd(&d_flag1, 0) == 0) __nanosleep(64);
    }
    __syncthreads();
    __threadfence();

    for (int i = tid; i < F_HID; i += 256) {
        s_sc[i] = d_scale[i];
        s_sh[i] = d_shift[i];
    }
    __syncthreads();

    float acc[2][4] = {};
    // store tile 0 (BN + cvt)
    {
        int cb = aseg;
#pragma unroll
        for (int j = 0; j < 2; j++) {
            float4 f = aReg[j];
            float4 sc = *(const float4*)(s_sc + cb + j * 4);
            float4 sh = *(const float4*)(s_sh + cb + j * 4);
            f.x = fmaxf(f.x * sc.x + sh.x, 0.0f);
            f.y = fmaxf(f.y * sc.y + sh.y, 0.0f);
            f.z = fmaxf(f.z * sc.z + sh.z, 0.0f);
            f.w = fmaxf(f.w * sc.w + sh.w, 0.0f);
            __half2 h0 = __floats2half2_rn(f.x, f.y);
            __half2 h1 = __floats2half2_rn(f.z, f.w);
            uint2 pk; pk.x = *(unsigned*)&h0; pk.y = *(unsigned*)&h1;
            *(uint2*)(As[0] + arow * APAD + aseg + j * 4) = pk;
        }
        *(uint4*)(Bs[0] + brow * APAD + bseg)     = bReg[0];
        *(uint4*)(Bs[0] + brow * APAD + bseg + 8) = bReg[1];
    }
    __syncthreads();

    for (int kt = 0; kt < 8; kt++) {
        int cur = kt & 1, nxt = cur ^ 1;
        if (kt < 7) {
            int k0n = (kt + 1) * 64;
            const float* Ap = A + (size_t)(bm + arow) * F_HID + k0n + aseg;
            aReg[0] = *(const float4*)(Ap);
            aReg[1] = *(const float4*)(Ap + 4);
            bReg[0] = *(const uint4*)(d_W2h + (size_t)(k0n + brow) * F_HID + bn + bseg);
            bReg[1] = *(const uint4*)(d_W2h + (size_t)(k0n + brow) * F_HID + bn + bseg + 8);
        }

#pragma unroll
        for (int kk = 0; kk < 64; kk += 16) {
            unsigned aF[4], bF[4];
            {
                unsigned addr = smem_u32(As[cur] + (warp_m * 16 + (lane & 15)) * APAD
                                            + kk + ((lane >> 4) << 3));
                asm volatile("ldmatrix.sync.aligned.m8n8.x4.shared.b16 {%0,%1,%2,%3}, [%4];"
                             : "=r"(aF[0]), "=r"(aF[1]), "=r"(aF[2]), "=r"(aF[3])
                             : "r"(addr));
            }
            {
                unsigned addr = smem_u32(Bs[cur] + (kk + (lane & 15)) * APAD
                                            + warp_n * 16 + ((lane >> 4) << 3));
                asm volatile("ldmatrix.sync.aligned.m8n8.x4.trans.shared.b16 {%0,%1,%2,%3}, [%4];"
                             : "=r"(bF[0]), "=r"(bF[1]), "=r"(bF[2]), "=r"(bF[3])
                             : "r"(addr));
            }
#pragma unroll
            for (int ni = 0; ni < 2; ni++) {
                asm volatile(
                    "mma.sync.aligned.m16n8k16.row.col.f32.f16.f16.f32 "
                    "{%0,%1,%2,%3}, {%4,%5,%6,%7}, {%8,%9}, {%0,%1,%2,%3};"
                    : "+f"(acc[ni][0]), "+f"(acc[ni][1]),
                      "+f"(acc[ni][2]), "+f"(acc[ni][3])
                    : "r"(aF[0]), "r"(aF[1]), "r"(aF[2]), "r"(aF[3]),
                      "r"(bF[ni * 2]), "r"(bF[ni * 2 + 1]));
            }
        }

        if (kt < 7) {
            int cb = (kt + 1) * 64 + aseg;
#pragma unroll
            for (int j = 0; j < 2; j++) {
                float4 f = aReg[j];
                float4 sc = *(const float4*)(s_sc + cb + j * 4);
                float4 sh = *(const float4*)(s_sh + cb + j * 4);
                f.x = fmaxf(f.x * sc.x + sh.x, 0.0f);
                f.y = fmaxf(f.y * sc.y + sh.y, 0.0f);
                f.z = fmaxf(f.z * sc.z + sh.z, 0.0f);
                f.w = fmaxf(f.w * sc.w + sh.w, 0.0f);
                __half2 h0 = __floats2half2_rn(f.x, f.y);
                __half2 h1 = __floats2half2_rn(f.z, f.w);
                uint2 pk; pk.x = *(unsigned*)&h0; pk.y = *(unsigned*)&h1;
                *(uint2*)(As[nxt] + arow * APAD + aseg + j * 4) = pk;
            }
            *(uint4*)(Bs[nxt] + brow * APAD + bseg)     = bReg[0];
            *(uint4*)(Bs[nxt] + brow * APAD + bseg + 8) = bReg[1];
            __syncthreads();
        }
    }

    // epilogue: fp16 store + attention dot partials
    int h = bn >> 7;
    int colh = (bn & 127) + warp_n * 16;
    float asv[2][2], adv[2][2];
#pragma unroll
    for (int ni = 0; ni < 2; ni++) {
        int c0 = colh + ni * 8 + (lane & 3) * 2;
        asv[ni][0] = att_s[h * C_HID + c0];
        asv[ni][1] = att_s[h * C_HID + c0 + 1];
        adv[ni][0] = att_d[h * C_HID + c0];
        adv[ni][1] = att_d[h * C_HID + c0 + 1];
    }
    {
        int row0 = bm + warp_m * 16 + (lane >> 2);
        int row1 = row0 + 8;
        float ps0 = 0.0f, pd0 = 0.0f, ps1 = 0.0f, pd1 = 0.0f;
#pragma unroll
        for (int ni = 0; ni < 2; ni++) {
            int col = bn + warp_n * 16 + ni * 8 + (lane & 3) * 2;
            __half2 h0 = __floats2half2_rn(acc[ni][0], acc[ni][1]);
            __half2 h1 = __floats2half2_rn(acc[ni][2], acc[ni][3]);
            *(__half2*)(d_h + (size_t)row0 * F_HID + col) = h0;
            *(__half2*)(d_h + (size_t)row1 * F_HID + col) = h1;
            ps0 += acc[ni][0] * asv[ni][0] + acc[ni][1] * asv[ni][1];
            ps1 += acc[ni][2] * asv[ni][0] + acc[ni][3] * asv[ni][1];
            pd0 += acc[ni][0] * adv[ni][0] + acc[ni][1] * adv[ni][1];
            pd1 += acc[ni][2] * adv[ni][0] + acc[ni][3] * adv[ni][1];
        }
#pragma unroll
        for (int o = 1; o < 4; o <<= 1) {
            ps0 += __shfl_xor_sync(0xffffffffu, ps0, o);
            ps1 += __shfl_xor_sync(0xffffffffu, ps1, o);
            pd0 += __shfl_xor_sync(0xffffffffu, pd0, o);
            pd1 += __shfl_xor_sync(0xffffffffu, pd1, o);
        }
        if ((lane & 3) == 0) {
            atomicAdd(&d_as[row0 * 4 + h], ps0);
            atomicAdd(&d_ad[row0 * 4 + h], pd0);
            atomicAdd(&d_as[row1 * 4 + h], ps1);
            atomicAdd(&d_ad[row1 * 4 + h], pd1);
        }
    }
}

// ---------------- edge head: BN2 stats + barrier + split-K x8 GEMM ----------
__global__ void __launch_bounds__(256) k_gemm_out(const float* __restrict__ A,
                                                  const float* __restrict__ B,
                                                  const int* __restrict__ mask,
                                                  float* __restrict__ out,
                                                  const float* __restrict__ g,
                                                  const float* __restrict__ b) {
    const int Nc = OUT_E;
    __shared__ float As[16][64];
    __shared__ float Bs[16][64];
    __shared__ int s_last;
    int tid = threadIdx.x;
    int bm = blockIdx.y * 64;
    int kbase = blockIdx.x * 64;
    int nblocks = gridDim.x * gridDim.y;             // 320
    int lb = blockIdx.y * gridDim.x + blockIdx.x;    // 0..319
    int tx = tid & 15, ty = tid >> 4;
    int ar = tid >> 2, ac = (tid & 3) << 2;
    int br = tid >> 4, bc = (tid & 15) << 2;

    // ---- BN2 partial stats: rows lb*8..+7, channels tid, tid+256 ----
    {
        int r0 = lb * 8;
        float s0 = 0.0f, q0 = 0.0f, s1 = 0.0f, q1 = 0.0f;
#pragma unroll
        for (int r = 0; r < 8; r++) {
            float v0 = d_agg[(size_t)(r0 + r) * F_HID + tid];
            float v1 = d_agg[(size_t)(r0 + r) * F_HID + tid + 256];
            s0 += v0; q0 += v0 * v0;
            s1 += v1; q1 += v1 * v1;
        }
        atomicAdd(&d_bnsum[tid], s0);
        atomicAdd(&d_bnsq[tid], q0);
        atomicAdd(&d_bnsum[tid + 256], s1);
        atomicAdd(&d_bnsq[tid + 256], q1);
    }
    __threadfence();
    __syncthreads();
    if (tid == 0) s_last = (atomicAdd(&d_ticket, 1) == nblocks - 1);
    __syncthreads();
    if (s_last) {
        for (int c = tid; c < F_HID; c += 256) {
            float mean = d_bnsum[c] * (1.0f / N_NODES);
            float var  = d_bnsq[c] * (1.0f / N_NODES) - mean * mean;
            float sc = rsqrtf(var + EPS_BN) * g[c];
            d_scale[c] = sc;
            d_shift[c] = b[c] - mean * sc;
            d_bnsum[c] = 0.0f;
            d_bnsq[c] = 0.0f;
        }
        __threadfence();
        __syncthreads();
        if (tid == 0) { d_ticket = 0; atomicExch(&d_flag2, 1); }
    }
    if (tid == 0) {
        while (atomicAdd(&d_flag2, 0) == 0) __nanosleep(64);
    }
    __syncthreads();
    __threadfence();

    float acc[4][4] = {};
    for (int k0 = kbase; k0 < kbase + 64; k0 += 16) {
        float4 av = *(const float4*)(A + (size_t)(bm + ar) * F_HID + k0 + ac);
        float4 sc = *(const float4*)(d_scale + k0 + ac);
        float4 sh = *(const float4*)(d_shift + k0 + ac);
        As[ac + 0][ar] = fmaxf(av.x * sc.x + sh.x, 0.0f);
        As[ac + 1][ar] = fmaxf(av.y * sc.y + sh.y, 0.0f);
        As[ac + 2][ar] = fmaxf(av.z * sc.z + sh.z, 0.0f);
        As[ac + 3][ar] = fmaxf(av.w * sc.w + sh.w, 0.0f);
        const float* Bp = B + (size_t)(k0 + br) * Nc;
        float4 bv;
        if (bc + 3 < Nc) bv = *(const float4*)(Bp + bc);
        else {
            bv.x = (bc + 0 < Nc) ? Bp[bc + 0] : 0.0f;
            bv.y = (bc + 1 < Nc) ? Bp[bc + 1] : 0.0f;
            bv.z = (bc + 2 < Nc) ? Bp[bc + 2] : 0.0f;
            bv.w = (bc + 3 < Nc) ? Bp[bc + 3] : 0.0f;
        }
        *(float4*)&Bs[br][bc] = bv;
        __syncthreads();
#pragma unroll
        for (int k = 0; k < 16; k++) {
            float a[4], bb[4];
#pragma unroll
            for (int i = 0; i < 4; i++) a[i] = As[k][(ty << 2) + i];
#pragma unroll
            for (int j = 0; j < 4; j++) bb[j] = Bs[k][(tx << 2) + j];
#pragma unroll
            for (int i = 0; i < 4; i++)
#pragma unroll
                for (int j = 0; j < 4; j++) acc[i][j] += a[i] * bb[j];
        }
        __syncthreads();
    }

#pragma unroll
    for (int i = 0; i < 4; i++) {
        int row = bm + (ty << 2) + i;
        float mk = (float)mask[row];
#pragma unroll
        for (int j = 0; j < 4; j++) {
            int col = (tx << 2) + j;
            if (col < Nc)
                atomicAdd(&out[(size_t)row * Nc + col], acc[i][j] * mk);
        }
    }
}

// ---------------- aggregation: 2 nodes/block, 64 thr/node, fused exp+sum ----
__global__ void __launch_bounds__(128) k_aggregate(const float* __restrict__ bias, int layer) {
    __shared__ int   s_off[2][CAP];
    __shared__ float s_a[2][4][CAP];
    __shared__ float s_adc[2][4];
    __shared__ float s_cf[4];
    int tid = threadIdx.x;
    int half = tid >> 6, t = tid & 63;
    int n = (blockIdx.x << 1) + half;
    int h = t >> 4;
    int sub = t & 15;
    if (t < 4) s_adc[half][t] = d_ad[n * 4 + t];
    if (tid < 4) s_cf[tid] = d_coef[layer * 4 + tid];
    __syncthreads();
    int deg = min(d_cursor[n << 5], CAP);
    int off = n * CAP;

    for (int i = t; i < deg; i += 64) {
        int s = d_csr_src[off + i];
        float ew = d_csr_ew[off + i];
        s_off[half][i] = s * (F_HID * 2);
        float4 a4 = *(const float4*)&d_as[s * 4];
        float l0 = a4.x + s_adc[half][0] + ew * s_cf[0];
        float l1 = a4.y + s_adc[half][1] + ew * s_cf[1];
        float l2 = a4.z + s_adc[half][2] + ew * s_cf[2];
        float l3 = a4.w + s_adc[half][3] + ew * s_cf[3];
        s_a[half][0][i] = (l0 > 0.0f) ? l0 : 0.2f * l0;
        s_a[half][1][i] = (l1 > 0.0f) ? l1 : 0.2f * l1;
        s_a[half][2][i] = (l2 > 0.0f) ? l2 : 0.2f * l2;
        s_a[half][3][i] = (l3 > 0.0f) ? l3 : 0.2f * l3;
    }
    __syncthreads();

    // per-head max
    float v = -1e30f;
    for (int i = sub; i < deg; i += 16) v = fmaxf(v, s_a[half][h][i]);
#pragma unroll
    for (int o = 8; o; o >>= 1) v = fmaxf(v, __shfl_xor_sync(0xffffffffu, v, o));

    // fused exp + sum for own head (warp-local)
    float rs = 0.0f;
    for (int i = sub; i < deg; i += 16) {
        float e = __expf(s_a[half][h][i] - v);
        s_a[half][h][i] = e;
        rs += e;
    }
#pragma unroll
    for (int o = 8; o; o >>= 1) rs += __shfl_xor_sync(0xffffffffu, rs, o);
    __syncwarp();

    const char* hb = (const char*)d_h + (t << 4);
    float acc[8] = {};
    int i = 0;
    for (; i + 4 <= deg; i += 4) {
        float4 wv = *(const float4*)&s_a[half][h][i];
        uint4 r0 = *(const uint4*)(hb + s_off[half][i]);
        uint4 r1 = *(const uint4*)(hb + s_off[half][i + 1]);
        uint4 r2 = *(const uint4*)(hb + s_off[half][i + 2]);
        uint4 r3 = *(const uint4*)(hb + s_off[half][i + 3]);
#pragma unroll
        for (int q = 0; q < 4; q++) {
            float2 f0 = __half22float2(*(__half2*)(&(&r0.x)[q]));
            float2 f1 = __half22float2(*(__half2*)(&(&r1.x)[q]));
            float2 f2 = __half22float2(*(__half2*)(&(&r2.x)[q]));
            float2 f3 = __half22float2(*(__half2*)(&(&r3.x)[q]));
            acc[q * 2 + 0] += wv.x * f0.x + wv.y * f1.x + wv.z * f2.x + wv.w * f3.x;
            acc[q * 2 + 1] += wv.x * f0.y + wv.y * f1.y + wv.z * f2.y + wv.w * f3.y;
        }
    }
    for (; i < deg; i++) {
        float wt = s_a[half][h][i];
        uint4 r = *(const uint4*)(hb + s_off[half][i]);
#pragma unroll
        for (int q = 0; q < 4; q++) {
            float2 f = __half22float2(*(__half2*)(&(&r.x)[q]));
            acc[q * 2 + 0] += wt * f.x;
            acc[q * 2 + 1] += wt * f.y;
        }
    }

    float inv = __fdividef(1.0f, rs + 1e-16f);
    float4 b0 = *(const float4*)(bias + (t << 3));
    float4 b1 = *(const float4*)(bias + (t << 3) + 4);
    float4 o0, o1;
    o0.x = acc[0] * inv + b0.x; o0.y = acc[1] * inv + b0.y;
    o0.z = acc[2] * inv + b0.z; o0.w = acc[3] * inv + b0.w;
    o1.x = acc[4] * inv + b1.x; o1.y = acc[5] * inv + b1.y;
    o1.z = acc[6] * inv + b1.z; o1.w = acc[7] * inv + b1.w;
    float* op = d_agg + (size_t)n * F_HID + (t << 3);
    *(float4*)(op) = o0;
    *(float4*)(op + 4) = o1;
}

// ---------------- launcher ----------------------------------------------------
extern "C" void kernel_launch(void* const* d_in, const int* in_sizes, int n_in,
                              void* d_out, int out_size) {
    const float* x    = (const float*)d_in[0];
    const int*   ei   = (const int*)d_in[1];
    const float* pos  = (const float*)d_in[2];
    const int*   mask = (const int*)d_in[3];
    const float* adj  = (const float*)d_in[4];
    const float* W1   = (const float*)d_in[5];
    const float* as1  = (const float*)d_in[6];
    const float* ad1  = (const float*)d_in[7];
    const float* We1  = (const float*)d_in[8];
    const float* ae1  = (const float*)d_in[9];
    const float* b1   = (const float*)d_in[10];
    const float* g1   = (const float*)d_in[11];
    const float* be1  = (const float*)d_in[12];
    const float* W2   = (const float*)d_in[13];
    const float* as2  = (const float*)d_in[14];
    const float* ad2  = (const float*)d_in[15];
    const float* We2  = (const float*)d_in[16];
    const float* ae2  = (const float*)d_in[17];
    const float* b2   = (const float*)d_in[18];
    const float* g2   = (const float*)d_in[19];
    const float* be2  = (const float*)d_in[20];
    const float* Wfc  = (const float*)d_in[21];
    const float* bfc  = (const float*)d_in[22];
    float* out = (float*)d_out;

    float *pagg;
    cudaGetSymbolAddress((void**)&pagg, d_agg);

    // preprocessing (convW + out-init + coef + zeroing + flags, one kernel)
    k_prep<<<128, 256>>>(W2, adj, bfc, mask, out, We1, ae1, We2, ae2);

    // fill (640 blocks) + GEMM1 (320 blocks) fused in one launch
    k_fill_gemm1<<<960, 256>>>(ei, pos, x, W1, as1, ad1);

    // ---- layer 1 ----
    k_aggregate<<<N_NODES / 2, 128>>>(b1, 0);

    // ---- layer 2: BN1 stats + barrier + HMMA (32x64 M-split, 640 blocks) ----
    k_gemm2_mma<<<dim3(F_HID / 64, N_NODES / 32), 256>>>(pagg, as2, ad2, g1, be1);
    k_aggregate<<<N_NODES / 2, 128>>>(b2, 1);

    // ---- edge head: BN2 stats + barrier + split-K x8 GEMM ----
    k_gemm_out<<<dim3(8, N_NODES / 64), 256>>>(pagg, Wfc, mask, out, g2, be2);
}